// round 9
// baseline (speedup 1.0000x reference)
#include <cuda_runtime.h>
#include <math.h>

// LIF_R step, N=8192. w @ g dominates: 256 MB fp32 streamed once from HBM.
// R9: split-K. Rows split into 8 chunks of 1024 floats -> 65536 tasks over
// 7296 resident warps (912 CTAs = 6/SM x 152 SMs, single wave, 75% occ).
// Static stride -> 8.98 avg / 9 max tasks per warp (0.2% imbalance), no
// atomics, no per-row barriers. Partials to __device__ scratch; kernel 2
// combines in fixed order + LIF pointwise. Deterministic.

#define N_NEURONS 8192
#define ROW_F4 2048                  // float4 per row
#define CHUNKS 8
#define CHUNK_F4 (ROW_F4 / CHUNKS)   // 256 float4 = 1024 floats per task
#define N_TASKS (N_NEURONS * CHUNKS) // 65536

#define THREADS 256
#define WARPS_PER_CTA 8
#define GRID1 912                    // 6 CTAs/SM * 152 SMs -> 7296 warps
#define N_WARPS (GRID1 * WARPS_PER_CTA)

#define C_M_INV 20.0f
#define F_V 0.15f
#define DELTA_V 12.0f

__device__ float g_partial[N_TASKS];   // 256 KB scratch, [row][chunk]

__global__ __launch_bounds__(THREADS, 6)
void lif_matvec_kernel(const float* __restrict__ g,
                       const float* __restrict__ w)
{
    __shared__ float sg[N_NEURONS];    // 32 KB

    {
        const float4* g4 = reinterpret_cast<const float4*>(g);
        float4* s4 = reinterpret_cast<float4*>(sg);
        #pragma unroll
        for (int i = threadIdx.x; i < ROW_F4; i += THREADS)
            s4[i] = g4[i];
    }
    __syncthreads();

    const int lane = threadIdx.x & 31;
    const int wgid = blockIdx.x * WARPS_PER_CTA + (threadIdx.x >> 5);
    const float4* __restrict__ sg4 = reinterpret_cast<const float4*>(sg);

    for (int t = wgid; t < N_TASKS; t += N_WARPS) {
        const int row = t >> 3;
        const int c   = t & 7;
        const float4* __restrict__ wr =
            reinterpret_cast<const float4*>(w + (size_t)row * N_NEURONS)
            + c * CHUNK_F4;
        const float4* __restrict__ gc = sg4 + c * CHUNK_F4;

        // 256 f4 / 32 lanes = 8 per lane; two 4-deep front-batched groups.
        float a0 = 0.0f, a1 = 0.0f;
        #pragma unroll
        for (int k = 0; k < CHUNK_F4; k += 128) {
            const int b = lane + k;
            float4 w0 = __ldcs(&wr[b]);
            float4 w1 = __ldcs(&wr[b + 32]);
            float4 w2 = __ldcs(&wr[b + 64]);
            float4 w3 = __ldcs(&wr[b + 96]);
            float4 g0 = gc[b];
            float4 g1 = gc[b + 32];
            float4 g2 = gc[b + 64];
            float4 g3 = gc[b + 96];
            a0 = fmaf(w0.x, g0.x, a0); a0 = fmaf(w0.y, g0.y, a0);
            a0 = fmaf(w0.z, g0.z, a0); a0 = fmaf(w0.w, g0.w, a0);
            a1 = fmaf(w1.x, g1.x, a1); a1 = fmaf(w1.y, g1.y, a1);
            a1 = fmaf(w1.z, g1.z, a1); a1 = fmaf(w1.w, g1.w, a1);
            a0 = fmaf(w2.x, g2.x, a0); a0 = fmaf(w2.y, g2.y, a0);
            a0 = fmaf(w2.z, g2.z, a0); a0 = fmaf(w2.w, g2.w, a0);
            a1 = fmaf(w3.x, g3.x, a1); a1 = fmaf(w3.y, g3.y, a1);
            a1 = fmaf(w3.z, g3.z, a1); a1 = fmaf(w3.w, g3.w, a1);
        }
        float acc = a0 + a1;

        #pragma unroll
        for (int off = 16; off > 0; off >>= 1)
            acc += __shfl_xor_sync(0xFFFFFFFFu, acc, off);

        if (lane == 0) g_partial[t] = acc;
    }
}

__global__ __launch_bounds__(256)
void lif_pointwise_kernel(const float* __restrict__ x_in,
                          const float* __restrict__ v,
                          const float* __restrict__ theta_s,
                          const float* __restrict__ v_rest,
                          float* __restrict__ out)
{
    const int r = blockIdx.x * 256 + threadIdx.x;
    if (r >= N_NEURONS) return;

    const float4* p = reinterpret_cast<const float4*>(&g_partial[r * CHUNKS]);
    float4 p0 = p[0];
    float4 p1 = p[1];
    // Fixed combination order -> deterministic.
    const float s = ((p0.x + p0.y) + (p0.z + p0.w))
                  + ((p1.x + p1.y) + (p1.z + p1.w));

    const float I  = s + x_in[r];
    const float vv = v[r];
    const float vr = v_rest[r];
    const float th = theta_s[r];

    const float v_next = vv + (vr - vv + I * C_M_INV);
    const float soft = 1.0f / (1.0f + expf(-(v_next - th)));
    const bool spiked = (v_next >= th);
    const float v_reset = vr + F_V * (vv - vr) - DELTA_V;

    out[r] = spiked ? v_reset : v_next;
    out[N_NEURONS + r] = soft;
}

extern "C" void kernel_launch(void* const* d_in, const int* in_sizes, int n_in,
                              void* d_out, int out_size)
{
    // metadata order: x_in, v, g, theta_s, w, v_rest, tau_g
    const float* x_in    = (const float*)d_in[0];
    const float* v       = (const float*)d_in[1];
    const float* g       = (const float*)d_in[2];
    const float* theta_s = (const float*)d_in[3];
    const float* w       = (const float*)d_in[4];
    const float* v_rest  = (const float*)d_in[5];
    float* out = (float*)d_out;

    lif_matvec_kernel<<<GRID1, THREADS>>>(g, w);
    lif_pointwise_kernel<<<N_NEURONS / 256, 256>>>(x_in, v, theta_s, v_rest, out);
}

// round 15
// speedup vs baseline: 1.0493x; 1.0493x over previous
#include <cuda_runtime.h>
#include <math.h>

// LIF_R step, N=8192. w @ g = 256 MB fp32 streamed once from HBM.
// R10 (6th submission; five broker timeouts): DRAM page-locality experiment.
// Each CTA owns a contiguous 16-row band and streams ONE row at a time
// (16 KB dense in-flight window) -> ~512 dense streams chip-wide instead of
// ~14000 interleaved 4KB streams (suspected HBM row-buffer thrash behind the
// 68% plateau). No per-row barrier: 16 per-thread accumulators, single
// end-phase reduction via smem + fused LIF.

#define N_NEURONS 8192
#define ROW_F4 2048                   // float4 per row
#define THREADS 256
#define ROWS_PER_CTA 16
#define GRID (N_NEURONS / ROWS_PER_CTA)   // 512, single wave at 4/SM

#define C_M_INV 20.0f
#define F_V 0.15f
#define DELTA_V 12.0f

__global__ __launch_bounds__(THREADS, 4)
void lif_r_kernel(const float* __restrict__ x_in,
                  const float* __restrict__ v,
                  const float* __restrict__ g,
                  const float* __restrict__ theta_s,
                  const float* __restrict__ w,
                  const float* __restrict__ v_rest,
                  float* __restrict__ out)
{
    __shared__ float sg[N_NEURONS];                    // 32 KB
    __shared__ float sred[ROWS_PER_CTA][THREADS];      // 16 KB

    // Stage g into shared once per CTA
    {
        const float4* g4 = reinterpret_cast<const float4*>(g);
        float4* s4 = reinterpret_cast<float4*>(sg);
        #pragma unroll
        for (int i = threadIdx.x; i < ROW_F4; i += THREADS)
            s4[i] = g4[i];
    }
    __syncthreads();

    const int tid  = threadIdx.x;
    const int base = blockIdx.x * ROWS_PER_CTA;
    const float4* __restrict__ sg4 = reinterpret_cast<const float4*>(sg);

    float areg[ROWS_PER_CTA];

    // One row at a time: dense 16KB contiguous in-flight window per CTA.
    #pragma unroll
    for (int rp = 0; rp < ROWS_PER_CTA; rp++) {
        const float4* __restrict__ wr =
            reinterpret_cast<const float4*>(w + (size_t)(base + rp) * N_NEURONS);

        // 2048 f4 / 256 threads = 8 per thread; two 4-deep batched groups.
        float a0 = 0.0f, a1 = 0.0f;
        #pragma unroll
        for (int k = 0; k < 8; k += 4) {
            const int b = tid + k * THREADS;
            float4 w0 = __ldcs(&wr[b]);
            float4 w1 = __ldcs(&wr[b + THREADS]);
            float4 w2 = __ldcs(&wr[b + 2 * THREADS]);
            float4 w3 = __ldcs(&wr[b + 3 * THREADS]);
            float4 g0 = sg4[b];
            float4 g1 = sg4[b + THREADS];
            float4 g2 = sg4[b + 2 * THREADS];
            float4 g3 = sg4[b + 3 * THREADS];
            a0 = fmaf(w0.x, g0.x, a0); a0 = fmaf(w0.y, g0.y, a0);
            a0 = fmaf(w0.z, g0.z, a0); a0 = fmaf(w0.w, g0.w, a0);
            a1 = fmaf(w1.x, g1.x, a1); a1 = fmaf(w1.y, g1.y, a1);
            a1 = fmaf(w1.z, g1.z, a1); a1 = fmaf(w1.w, g1.w, a1);
            a0 = fmaf(w2.x, g2.x, a0); a0 = fmaf(w2.y, g2.y, a0);
            a0 = fmaf(w2.z, g2.z, a0); a0 = fmaf(w2.w, g2.w, a0);
            a1 = fmaf(w3.x, g3.x, a1); a1 = fmaf(w3.y, g3.y, a1);
            a1 = fmaf(w3.z, g3.z, a1); a1 = fmaf(w3.w, g3.w, a1);
        }
        areg[rp] = a0 + a1;
    }

    // Single end-phase reduction: dump partials, one barrier, 8 warps
    // reduce 2 rows each, fused LIF on lane 0.
    #pragma unroll
    for (int rp = 0; rp < ROWS_PER_CTA; rp++)
        sred[rp][tid] = areg[rp];
    __syncthreads();

    const int lane = tid & 31;
    const int wid  = tid >> 5;

    #pragma unroll
    for (int h = 0; h < 2; h++) {
        const int rp  = wid * 2 + h;
        const int row = base + rp;

        float s = 0.0f;
        #pragma unroll
        for (int j = 0; j < THREADS / 32; j++)
            s += sred[rp][lane + 32 * j];

        #pragma unroll
        for (int off = 16; off > 0; off >>= 1)
            s += __shfl_xor_sync(0xFFFFFFFFu, s, off);

        if (lane == 0) {
            const float I  = s + x_in[row];
            const float vv = v[row];
            const float vr = v_rest[row];
            const float th = theta_s[row];

            const float v_next = vv + (vr - vv + I * C_M_INV);
            const float soft = 1.0f / (1.0f + expf(-(v_next - th)));
            const bool spiked = (v_next >= th);
            const float v_reset = vr + F_V * (vv - vr) - DELTA_V;

            out[row] = spiked ? v_reset : v_next;
            out[N_NEURONS + row] = soft;
        }
    }
}

extern "C" void kernel_launch(void* const* d_in, const int* in_sizes, int n_in,
                              void* d_out, int out_size)
{
    // metadata order: x_in, v, g, theta_s, w, v_rest, tau_g
    const float* x_in    = (const float*)d_in[0];
    const float* v       = (const float*)d_in[1];
    const float* g       = (const float*)d_in[2];
    const float* theta_s = (const float*)d_in[3];
    const float* w       = (const float*)d_in[4];
    const float* v_rest  = (const float*)d_in[5];
    float* out = (float*)d_out;

    lif_r_kernel<<<GRID, THREADS>>>(x_in, v, g, theta_s, w, v_rest, out);
}

// round 16
// speedup vs baseline: 1.2281x; 1.1703x over previous
#include <cuda_runtime.h>
#include <math.h>
#include <stdint.h>

// LIF_R step, N=8192. w @ g = 256 MB fp32 streamed once from HBM.
// R16: TMA experiment. All LDG-based kernels (5 structures) plateau at
// 65-69% of HBM spec. Test whether the limiter is SM-side LDG request
// tracking: fetch w via cp.async.bulk (8 KB chunks, 4-deep ring per CTA,
// mbarrier tx accounting) -> in-flight bytes guaranteed by construction,
// independent of the L1tex/LDG path. Band structure from R10 (512 CTAs x
// 16 contiguous rows), g read via L1-resident LDG, single-barrier epilogue.

#define N_NEURONS 8192
#define THREADS 256
#define ROWS_PER_CTA 16
#define GRID (N_NEURONS / ROWS_PER_CTA)    // 512
#define CHUNK_BYTES 8192                    // quarter row
#define CHUNK_F4 512
#define NBUF 4
#define NCHUNK (ROWS_PER_CTA * 4)           // 64 chunks per CTA band

#define C_M_INV 20.0f
#define F_V 0.15f
#define DELTA_V 12.0f

__device__ __forceinline__ uint32_t smem_u32(const void* p) {
    return (uint32_t)__cvta_generic_to_shared(p);
}
__device__ __forceinline__ void mbar_init(uint32_t a, uint32_t cnt) {
    asm volatile("mbarrier.init.shared.b64 [%0], %1;" :: "r"(a), "r"(cnt) : "memory");
}
__device__ __forceinline__ void mbar_expect_tx(uint32_t a, uint32_t bytes) {
    asm volatile("mbarrier.arrive.expect_tx.shared.b64 _, [%0], %1;"
                 :: "r"(a), "r"(bytes) : "memory");
}
__device__ __forceinline__ void bulk_g2s(uint32_t dst, const void* src,
                                         uint32_t bytes, uint32_t mbar) {
    asm volatile(
        "cp.async.bulk.shared::cta.global.mbarrier::complete_tx::bytes "
        "[%0], [%1], %2, [%3];"
        :: "r"(dst), "l"(src), "r"(bytes), "r"(mbar) : "memory");
}
__device__ __forceinline__ void mbar_wait(uint32_t a, uint32_t parity) {
    asm volatile(
        "{\n\t.reg .pred P;\n"
        "W_%=:\n\t"
        "mbarrier.try_wait.parity.acquire.cta.shared::cta.b64 P, [%0], %1;\n\t"
        "@!P bra W_%=;\n\t}"
        :: "r"(a), "r"(parity) : "memory");
}

__global__ __launch_bounds__(THREADS, 4)
void lif_r_kernel(const float* __restrict__ x_in,
                  const float* __restrict__ v,
                  const float* __restrict__ g,
                  const float* __restrict__ theta_s,
                  const float* __restrict__ w,
                  const float* __restrict__ v_rest,
                  float* __restrict__ out)
{
    __shared__ __align__(128) float4 sbuf[NBUF][CHUNK_F4];  // 32 KB ring
    __shared__ __align__(8) uint64_t smb[NBUF];

    const int tid = threadIdx.x;
    const char* wband = reinterpret_cast<const char*>(w)
        + (size_t)blockIdx.x * ((size_t)ROWS_PER_CTA * N_NEURONS * sizeof(float));

    if (tid == 0) {
        #pragma unroll
        for (int b = 0; b < NBUF; b++)
            mbar_init(smem_u32(&smb[b]), 1);
    }
    __syncthreads();
    if (tid == 0) {
        asm volatile("fence.proxy.async.shared::cta;" ::: "memory");
        // Prologue: fill the 4-deep ring.
        #pragma unroll
        for (int b = 0; b < NBUF; b++) {
            uint32_t mb = smem_u32(&smb[b]);
            mbar_expect_tx(mb, CHUNK_BYTES);
            bulk_g2s(smem_u32(&sbuf[b][0]), wband + (size_t)b * CHUNK_BYTES,
                     CHUNK_BYTES, mb);
        }
    }

    float areg[ROWS_PER_CTA];
    #pragma unroll
    for (int i = 0; i < ROWS_PER_CTA; i++) areg[i] = 0.0f;

    const float4* __restrict__ g4 = reinterpret_cast<const float4*>(g);

    // Chunk k = rp*4 + q covers quarter q of band row rp. Buffer = q,
    // parity = rp & 1 (each buffer is used 16 times).
    #pragma unroll
    for (int rp = 0; rp < ROWS_PER_CTA; rp++) {
        #pragma unroll
        for (int q = 0; q < 4; q++) {
            const int k = rp * 4 + q;
            const uint32_t mb = smem_u32(&smb[q]);
            mbar_wait(mb, (uint32_t)(rp & 1));

            const float4* wb = sbuf[q];
            float4 w0 = wb[tid];
            float4 w1 = wb[tid + 256];
            float4 g0 = __ldg(&g4[q * CHUNK_F4 + tid]);
            float4 g1 = __ldg(&g4[q * CHUNK_F4 + tid + 256]);

            float acc = areg[rp];
            acc = fmaf(w0.x, g0.x, acc); acc = fmaf(w0.y, g0.y, acc);
            acc = fmaf(w0.z, g0.z, acc); acc = fmaf(w0.w, g0.w, acc);
            acc = fmaf(w1.x, g1.x, acc); acc = fmaf(w1.y, g1.y, acc);
            acc = fmaf(w1.z, g1.z, acc); acc = fmaf(w1.w, g1.w, acc);
            areg[rp] = acc;

            __syncthreads();   // all threads done reading buffer q
            if (tid == 0 && k + NBUF < NCHUNK) {
                mbar_expect_tx(mb, CHUNK_BYTES);
                bulk_g2s(smem_u32(&sbuf[q][0]),
                         wband + (size_t)(k + NBUF) * CHUNK_BYTES,
                         CHUNK_BYTES, mb);
            }
        }
    }

    // Epilogue: reuse the ring smem for the reduction (last loop iteration
    // ended with __syncthreads, so all consumption is done).
    float* sred = reinterpret_cast<float*>(sbuf);  // 16 KB of 32 KB
    #pragma unroll
    for (int rp = 0; rp < ROWS_PER_CTA; rp++)
        sred[rp * THREADS + tid] = areg[rp];
    __syncthreads();

    const int lane = tid & 31;
    const int wid  = tid >> 5;
    const int base = blockIdx.x * ROWS_PER_CTA;

    #pragma unroll
    for (int h = 0; h < 2; h++) {
        const int rp  = wid * 2 + h;
        const int row = base + rp;

        float s = 0.0f;
        #pragma unroll
        for (int j = 0; j < THREADS / 32; j++)
            s += sred[rp * THREADS + lane + 32 * j];

        #pragma unroll
        for (int off = 16; off > 0; off >>= 1)
            s += __shfl_xor_sync(0xFFFFFFFFu, s, off);

        if (lane == 0) {
            const float I  = s + x_in[row];
            const float vv = v[row];
            const float vr = v_rest[row];
            const float th = theta_s[row];

            const float v_next = vv + (vr - vv + I * C_M_INV);
            const float soft = 1.0f / (1.0f + expf(-(v_next - th)));
            const bool spiked = (v_next >= th);
            const float v_reset = vr + F_V * (vv - vr) - DELTA_V;

            out[row] = spiked ? v_reset : v_next;
            out[N_NEURONS + row] = soft;
        }
    }
}

extern "C" void kernel_launch(void* const* d_in, const int* in_sizes, int n_in,
                              void* d_out, int out_size)
{
    // metadata order: x_in, v, g, theta_s, w, v_rest, tau_g
    const float* x_in    = (const float*)d_in[0];
    const float* v       = (const float*)d_in[1];
    const float* g       = (const float*)d_in[2];
    const float* theta_s = (const float*)d_in[3];
    const float* w       = (const float*)d_in[4];
    const float* v_rest  = (const float*)d_in[5];
    float* out = (float*)d_out;

    lif_r_kernel<<<GRID, THREADS>>>(x_in, v, g, theta_s, w, v_rest, out);
}